// round 1
// baseline (speedup 1.0000x reference)
#include <cuda_runtime.h>
#include <cuda_bf16.h>

#define B_MAX   8192
#define ROW_T   256     // threads per block (one row per thread)
#define NCOL    8       // column slices
#define TILE    256     // smem column tile

// Device scratch (no allocation allowed)
__device__ float g_p[B_MAX];
__device__ float g_t[B_MAX];
__device__ int   g_m;
__device__ float g_sum;

__global__ void k_init() {
    g_m = 0;
    g_sum = 0.0f;
}

// Compact flagged rows: gather (pred, fracTime) where ifMOF == 1.
// Order is irrelevant: the pair sum is permutation-invariant.
__global__ void k_compact(const float* __restrict__ pred,
                          const float* __restrict__ gt,
                          const int* __restrict__ ft_idx,
                          const int* __restrict__ fm_idx,
                          int n) {
    int i = blockIdx.x * blockDim.x + threadIdx.x;
    if (i >= n) return;
    int ft = ft_idx[0];
    int fm = fm_idx[0];
    float w = gt[i * 2 + fm];
    if (w == 1.0f) {
        int idx = atomicAdd(&g_m, 1);
        g_p[idx] = pred[i];
        g_t[idx] = gt[i * 2 + ft];
    }
}

// Full symmetric m x m sum of relu((p_i-p_j)*(t_i-t_j)).
// Diagonal is zero; triu sum = total / 2.
__global__ __launch_bounds__(ROW_T, 8)
void k_main() {
    __shared__ float2 sj[TILE];
    __shared__ float red[ROW_T / 32];

    const int m = g_m;
    const int rb = blockIdx.x;
    const int cb = blockIdx.y;

    if (rb * ROW_T >= m) return;  // whole block out of range (uniform)

    const int i = rb * ROW_T + threadIdx.x;
    const bool active = (i < m);
    float pi = 0.0f, ti = 0.0f;
    if (active) { pi = g_p[i]; ti = g_t[i]; }

    // Column slice [jstart, jend) of [0, m)
    const int jstart = (int)((long long)cb * m / NCOL);
    const int jend   = (int)((long long)(cb + 1) * m / NCOL);

    float acc = 0.0f;
    for (int j0 = jstart; j0 < jend; j0 += TILE) {
        const int cnt = min(TILE, jend - j0);
        __syncthreads();
        if (threadIdx.x < cnt) {
            sj[threadIdx.x] = make_float2(g_p[j0 + threadIdx.x],
                                          g_t[j0 + threadIdx.x]);
        }
        __syncthreads();
        if (active) {
            #pragma unroll 8
            for (int j = 0; j < cnt; ++j) {
                float2 v = sj[j];           // broadcast LDS.64
                float dp = pi - v.x;
                float dt = ti - v.y;
                acc += fmaxf(dp * dt, 0.0f);
            }
        }
    }

    // warp reduce
    #pragma unroll
    for (int o = 16; o > 0; o >>= 1)
        acc += __shfl_down_sync(0xffffffffu, acc, o);
    if ((threadIdx.x & 31) == 0) red[threadIdx.x >> 5] = acc;
    __syncthreads();
    if (threadIdx.x < (ROW_T / 32)) {
        float v = red[threadIdx.x];
        #pragma unroll
        for (int o = (ROW_T / 64); o > 0; o >>= 1)
            v += __shfl_down_sync(0xffu, v, o);
        if (threadIdx.x == 0) atomicAdd(&g_sum, v);
    }
}

// out = (g_sum/2) / 100 / (m*(m-1)/2) = g_sum / (100 * m * (m-1))
__global__ void k_final(float* out) {
    double m = (double)g_m;
    out[0] = (float)((double)g_sum / (100.0 * m * (m - 1.0)));
}

extern "C" void kernel_launch(void* const* d_in, const int* in_sizes, int n_in,
                              void* d_out, int out_size) {
    const float* pred = (const float*)d_in[0];
    const float* gt   = (const float*)d_in[1];
    const int* ft     = (const int*)d_in[2];
    const int* fm     = (const int*)d_in[3];
    float* out        = (float*)d_out;
    const int n = in_sizes[0];

    k_init<<<1, 1>>>();
    k_compact<<<(n + 255) / 256, 256>>>(pred, gt, ft, fm, n);
    dim3 grid((B_MAX + ROW_T - 1) / ROW_T, NCOL);  // inactive row-blocks exit fast
    k_main<<<grid, ROW_T>>>();
    k_final<<<1, 1>>>(out);
}